// round 7
// baseline (speedup 1.0000x reference)
#include <cuda_runtime.h>
#include <cuda_bf16.h>

#define B_  2
#define L_  24
#define C_  16
#define H_  64
#define W_  64
#define HW_ 4096
#define KCH 6

// Channel-grouped scratch: [B*L][4 groups][HW] float4 (4 channels per element).
__device__ float4 g_imgT[(size_t)B_ * L_ * 4 * HW_];
// Cumulative flow scratch: [B][L][HW] float2 (x,y per pixel).
__device__ float2 g_cum[(size_t)B_ * L_ * HW_];

// (t, k0) chunk table: for each t, chunks of <=KCH k-values. 60 entries.
__constant__ short2 g_chunks[60] = {
    {0,0},{1,0},{2,0},{3,0},{4,0},{5,0},
    {6,0},{6,6},{7,0},{7,6},{8,0},{8,6},{9,0},{9,6},{10,0},{10,6},{11,0},{11,6},
    {12,0},{12,6},{12,12},{13,0},{13,6},{13,12},{14,0},{14,6},{14,12},
    {15,0},{15,6},{15,12},{16,0},{16,6},{16,12},{17,0},{17,6},{17,12},
    {18,0},{18,6},{18,12},{18,18},{19,0},{19,6},{19,12},{19,18},
    {20,0},{20,6},{20,12},{20,18},{21,0},{21,6},{21,12},{21,18},
    {22,0},{22,6},{22,12},{22,18},{23,0},{23,6},{23,12},{23,18}
};

// Merged prologue. Blocks [0, 768): NCHW -> group-of-4 transpose, 4 pixels
// per thread via a 4x4 register transpose (4x LDG.128 -> 4x STG.128).
// Blocks [768, 800): flow cumsum along L.
__global__ __launch_bounds__(256) void prep_kernel(
    const float* __restrict__ images,   // [B, L, C, H, W]
    const float* __restrict__ flows)    // [B, L, 2, H, W]
{
    const int bid = blockIdx.x;
    if (bid < 768) {
        // linear id over (bl, grp, pix4): 48 * 4 * 1024 = 196608 threads
        const int id   = bid * 256 + threadIdx.x;
        const int pix4 = (id & 1023) * 4;         // 4-pixel base
        const int grp  = (id >> 10) & 3;
        const int bl   = id >> 12;                // 0..47
        const float4* src = (const float4*)(images + ((size_t)bl * C_ + grp * 4) * HW_ + pix4);
        float4 r0 = src[0];
        float4 r1 = src[HW_ / 4];
        float4 r2 = src[2 * (HW_ / 4)];
        float4 r3 = src[3 * (HW_ / 4)];
        float4* dst = g_imgT + ((size_t)bl * 4 + grp) * HW_ + pix4;
        dst[0] = make_float4(r0.x, r1.x, r2.x, r3.x);
        dst[1] = make_float4(r0.y, r1.y, r2.y, r3.y);
        dst[2] = make_float4(r0.z, r1.z, r2.z, r3.z);
        dst[3] = make_float4(r0.w, r1.w, r2.w, r3.w);
    } else {
        const int id  = (bid - 768) * 256 + threadIdx.x;   // 0..8191
        const int pix = id & (HW_ - 1);
        const int b   = id >> 12;
        const float* fp = flows + (size_t)b * L_ * 2 * HW_ + pix;
        float2* cp = g_cum + (size_t)b * L_ * HW_ + pix;
        float sx = 0.f, sy = 0.f;
#pragma unroll
        for (int k = 0; k < L_; ++k) {
            sx += fp[(size_t)k * 2 * HW_];
            sy += fp[(size_t)k * 2 * HW_ + HW_];
            cp[(size_t)k * HW_] = make_float2(sx, sy);
        }
    }
}

__device__ __forceinline__ void fma4(float4& a, float s, float4 v) {
    a.x += s * v.x; a.y += s * v.y; a.z += s * v.z; a.w += s * v.w;
}

// One bilinear-tap step for all 16 channels (4 float4 groups).
__device__ __forceinline__ void gsp_step(
    int k, int w, int h, float2 cumt, const float2* __restrict__ cumb,
    const float4* __restrict__ gbase, float4 acc[4])
{
    const float2 ckf = cumb[(size_t)k * HW_];
    float relx = cumt.x - ckf.x;   // exactly 0 when k==t
    float rely = cumt.y - ckf.y;

    // align_corners=False: base grid == pixel centers
    float ix = (float)w + 32.f * relx;
    ix -= 64.f * floorf((ix + 0.5f) * 0.015625f);   // wrap x into [-0.5, 63.5)
    float iy = (float)h + 32.f * rely;

    float x0f = floorf(ix), y0f = floorf(iy);
    int   x0  = (int)x0f,   y0  = (int)y0f;
    float wx1 = ix - x0f,   wy1 = iy - y0f;
    float wx0 = 1.f - wx1,  wy0 = 1.f - wy1;

    // x0 in [-1, 63] by construction; x1 = x0+1 in [0, 64]
    bool vx0 = (x0 >= 0);
    bool vx1 = (x0 < W_ - 1);
    bool vy0 = (y0 >= 0) && (y0 <= H_ - 1);
    bool vy1 = (y0 >= -1) && (y0 < H_ - 1);

    float w00 = wx0 * wy0 * (float)(vx0 && vy0);
    float w01 = wx1 * wy0 * (float)(vx1 && vy0);
    float w10 = wx0 * wy1 * (float)(vx0 && vy1);
    float w11 = wx1 * wy1 * (float)(vx1 && vy1);

    int cx0 = max(x0, 0),              cx1 = min(x0 + 1, W_ - 1);
    int cy0 = min(max(y0, 0), H_ - 1), cy1 = min(max(y0 + 1, 0), H_ - 1);

    const int o00 = cy0 * W_ + cx0, o01 = cy0 * W_ + cx1;
    const int o10 = cy1 * W_ + cx0, o11 = cy1 * W_ + cx1;

    const float4* gk = gbase + (size_t)k * 4 * HW_;
#pragma unroll
    for (int g = 0; g < 4; ++g) {
        const float4* p = gk + (size_t)g * HW_;
        fma4(acc[g], w00, p[o00]);
        fma4(acc[g], w01, p[o01]);
        fma4(acc[g], w10, p[o10]);
        fma4(acc[g], w11, p[o11]);
    }
}

// out[b,t,c,h,w] += sum_{k in chunk} bilinear taps (all 16 channels/thread).
// Block = (pixtile, chunk, b); <= KCH k-iterations per block.
__global__ __launch_bounds__(256, 3) void gsp_kernel(
    float* __restrict__ out)            // [B, L, C, H, W]
{
    const int b    = blockIdx.z;
    const short2 ck_ = g_chunks[blockIdx.y];
    const int t    = ck_.x;
    const int k0   = ck_.y;
    const int kend = min(k0 + KCH, t + 1);
    const int pix  = blockIdx.x * blockDim.x + threadIdx.x;
    const int h    = pix >> 6;
    const int w    = pix & 63;

    float4 acc[4];
#pragma unroll
    for (int g = 0; g < 4; ++g) acc[g] = make_float4(0.f, 0.f, 0.f, 0.f);

    const float2* cumb = g_cum + (size_t)b * L_ * HW_ + pix;
    const float2 cumt = cumb[(size_t)t * HW_];
    const float4* gbase = g_imgT + (size_t)b * L_ * 4 * HW_;

#pragma unroll 2
    for (int k = k0; k < kend; ++k)
        gsp_step(k, w, h, cumt, cumb, gbase, acc);

    float* op = out + ((size_t)b * L_ + t) * C_ * HW_ + pix;
    if (t < KCH) {   // single writer block: plain stores
#pragma unroll
        for (int g = 0; g < 4; ++g) {
            op[(size_t)(4*g+0) * HW_] = acc[g].x;
            op[(size_t)(4*g+1) * HW_] = acc[g].y;
            op[(size_t)(4*g+2) * HW_] = acc[g].z;
            op[(size_t)(4*g+3) * HW_] = acc[g].w;
        }
    } else {
#pragma unroll
        for (int g = 0; g < 4; ++g) {
            atomicAdd(op + (size_t)(4*g+0) * HW_, acc[g].x);
            atomicAdd(op + (size_t)(4*g+1) * HW_, acc[g].y);
            atomicAdd(op + (size_t)(4*g+2) * HW_, acc[g].z);
            atomicAdd(op + (size_t)(4*g+3) * HW_, acc[g].w);
        }
    }
}

extern "C" void kernel_launch(void* const* d_in, const int* in_sizes, int n_in,
                              void* d_out, int out_size)
{
    const float* flows  = (const float*)d_in[0];   // [2,24,2,64,64]
    const float* images = (const float*)d_in[1];   // [2,24,16,64,64]
    float*       out    = (float*)d_out;           // [2,24,16,64,64]

    // Zero only the atomically-accumulated region (t >= KCH).
    size_t skip = (size_t)KCH * C_ * HW_;
    for (int b = 0; b < B_; ++b) {
        float* p = out + (size_t)b * L_ * C_ * HW_;
        cudaMemsetAsync(p + skip, 0, ((size_t)L_ * C_ * HW_ - skip) * sizeof(float), 0);
    }

    prep_kernel<<<800, 256>>>(images, flows);      // transpose + cumsum, one launch

    dim3 grid(HW_ / 256, 60, B_);                  // (16, 60, 2)
    gsp_kernel<<<grid, 256>>>(out);
}

// round 8
// speedup vs baseline: 1.0997x; 1.0997x over previous
#include <cuda_runtime.h>
#include <cuda_bf16.h>

#define B_  2
#define L_  24
#define C_  16
#define H_  64
#define W_  64
#define HW_ 4096
#define KCH 6

// Channel-grouped scratch: [B*L][4 groups][HW] float4 (4 channels per element).
__device__ float4 g_imgT[(size_t)B_ * L_ * 4 * HW_];
// Cumulative flow scratch: [B][L][HW] float2 (x,y per pixel).
__device__ float2 g_cum[(size_t)B_ * L_ * HW_];

// (t, k0) chunk table: for each t, chunks of <=KCH k-values. 60 entries.
__constant__ short2 g_chunks[60] = {
    {0,0},{1,0},{2,0},{3,0},{4,0},{5,0},
    {6,0},{6,6},{7,0},{7,6},{8,0},{8,6},{9,0},{9,6},{10,0},{10,6},{11,0},{11,6},
    {12,0},{12,6},{12,12},{13,0},{13,6},{13,12},{14,0},{14,6},{14,12},
    {15,0},{15,6},{15,12},{16,0},{16,6},{16,12},{17,0},{17,6},{17,12},
    {18,0},{18,6},{18,12},{18,18},{19,0},{19,6},{19,12},{19,18},
    {20,0},{20,6},{20,12},{20,18},{21,0},{21,6},{21,12},{21,18},
    {22,0},{22,6},{22,12},{22,18},{23,0},{23,6},{23,12},{23,18}
};

// Merged prologue. Blocks [0, 768): NCHW -> group-of-4 transpose, 4 pixels
// per thread via a 4x4 register transpose (4x LDG.128 -> 4x STG.128).
// Blocks [768, 800): flow cumsum along L.
__global__ __launch_bounds__(256) void prep_kernel(
    const float* __restrict__ images,   // [B, L, C, H, W]
    const float* __restrict__ flows)    // [B, L, 2, H, W]
{
    const int bid = blockIdx.x;
    if (bid < 768) {
        // linear id over (bl, grp, pix4): 48 * 4 * 1024 = 196608 threads
        const int id   = bid * 256 + threadIdx.x;
        const int pix4 = (id & 1023) * 4;         // 4-pixel base
        const int grp  = (id >> 10) & 3;
        const int bl   = id >> 12;                // 0..47
        const float4* src = (const float4*)(images + ((size_t)bl * C_ + grp * 4) * HW_ + pix4);
        float4 r0 = src[0];
        float4 r1 = src[HW_ / 4];
        float4 r2 = src[2 * (HW_ / 4)];
        float4 r3 = src[3 * (HW_ / 4)];
        float4* dst = g_imgT + ((size_t)bl * 4 + grp) * HW_ + pix4;
        dst[0] = make_float4(r0.x, r1.x, r2.x, r3.x);
        dst[1] = make_float4(r0.y, r1.y, r2.y, r3.y);
        dst[2] = make_float4(r0.z, r1.z, r2.z, r3.z);
        dst[3] = make_float4(r0.w, r1.w, r2.w, r3.w);
    } else {
        const int id  = (bid - 768) * 256 + threadIdx.x;   // 0..8191
        const int pix = id & (HW_ - 1);
        const int b   = id >> 12;
        const float* fp = flows + (size_t)b * L_ * 2 * HW_ + pix;
        float2* cp = g_cum + (size_t)b * L_ * HW_ + pix;
        float sx = 0.f, sy = 0.f;
#pragma unroll
        for (int k = 0; k < L_; ++k) {
            sx += fp[(size_t)k * 2 * HW_];
            sy += fp[(size_t)k * 2 * HW_ + HW_];
            cp[(size_t)k * HW_] = make_float2(sx, sy);
        }
    }
}

__device__ __forceinline__ void fma4(float4& a, float s, float4 v) {
    a.x += s * v.x; a.y += s * v.y; a.z += s * v.z; a.w += s * v.w;
}

// One bilinear-tap step for 8 channels (2 float4 groups).
__device__ __forceinline__ void gsp_step(
    int k, int w, int h, float2 cumt, const float2* __restrict__ cumb,
    const float4* __restrict__ g0base, float4& acc0, float4& acc1)
{
    const float2 ckf = cumb[(size_t)k * HW_];
    float relx = cumt.x - ckf.x;   // exactly 0 when k==t
    float rely = cumt.y - ckf.y;

    // align_corners=False: base grid == pixel centers
    float ix = (float)w + 32.f * relx;
    ix -= 64.f * floorf((ix + 0.5f) * 0.015625f);   // wrap x into [-0.5, 63.5)
    float iy = (float)h + 32.f * rely;

    float x0f = floorf(ix), y0f = floorf(iy);
    int   x0  = (int)x0f,   y0  = (int)y0f;
    float wx1 = ix - x0f,   wy1 = iy - y0f;
    float wx0 = 1.f - wx1,  wy0 = 1.f - wy1;

    // x0 in [-1, 63] by construction; x1 = x0+1 in [0, 64]
    bool vx0 = (x0 >= 0);
    bool vx1 = (x0 < W_ - 1);
    bool vy0 = (y0 >= 0) && (y0 <= H_ - 1);
    bool vy1 = (y0 >= -1) && (y0 < H_ - 1);

    float w00 = wx0 * wy0 * (float)(vx0 && vy0);
    float w01 = wx1 * wy0 * (float)(vx1 && vy0);
    float w10 = wx0 * wy1 * (float)(vx0 && vy1);
    float w11 = wx1 * wy1 * (float)(vx1 && vy1);

    int cx0 = max(x0, 0),              cx1 = min(x0 + 1, W_ - 1);
    int cy0 = min(max(y0, 0), H_ - 1), cy1 = min(max(y0 + 1, 0), H_ - 1);

    const int o00 = cy0 * W_ + cx0, o01 = cy0 * W_ + cx1;
    const int o10 = cy1 * W_ + cx0, o11 = cy1 * W_ + cx1;

    const float4* g0 = g0base + (size_t)k * 4 * HW_;   // group A plane for frame k
    const float4* g1 = g0 + HW_;                       // group B plane

    fma4(acc0, w00, g0[o00]); fma4(acc0, w01, g0[o01]);
    fma4(acc0, w10, g0[o10]); fma4(acc0, w11, g0[o11]);
    fma4(acc1, w00, g1[o00]); fma4(acc1, w01, g1[o01]);
    fma4(acc1, w10, g1[o10]); fma4(acc1, w11, g1[o11]);
}

// out[b,t,c,h,w] += sum_{k in chunk} bilinear taps (8 channels per thread).
// Block = (pixtile, chunk, b*2+half); <= KCH k-iterations per block.
__global__ __launch_bounds__(256) void gsp_kernel(
    float* __restrict__ out)            // [B, L, C, H, W]
{
    const int b    = blockIdx.z >> 1;
    const int half = blockIdx.z & 1;          // 0 -> groups 0,1 (c0..7); 1 -> groups 2,3
    const short2 ck_ = g_chunks[blockIdx.y];
    const int t    = ck_.x;
    const int k0   = ck_.y;
    const int kend = min(k0 + KCH, t + 1);
    const int pix  = blockIdx.x * blockDim.x + threadIdx.x;
    const int h    = pix >> 6;
    const int w    = pix & 63;

    float4 acc0 = make_float4(0.f, 0.f, 0.f, 0.f);
    float4 acc1 = make_float4(0.f, 0.f, 0.f, 0.f);

    const float2* cumb = g_cum + (size_t)b * L_ * HW_ + pix;
    const float2 cumt = cumb[(size_t)t * HW_];
    // plane base for (b, frame 0, group half*2)
    const float4* g0base = g_imgT + ((size_t)b * L_ * 4 + half * 2) * HW_;

    if (kend - k0 == KCH) {
#pragma unroll
        for (int j = 0; j < KCH; ++j)
            gsp_step(k0 + j, w, h, cumt, cumb, g0base, acc0, acc1);
    } else {
#pragma unroll 3
        for (int k = k0; k < kend; ++k)
            gsp_step(k, w, h, cumt, cumb, g0base, acc0, acc1);
    }

    float* op = out + (((size_t)b * L_ + t) * C_ + half * 8) * HW_ + pix;
    float a[8] = {acc0.x, acc0.y, acc0.z, acc0.w, acc1.x, acc1.y, acc1.z, acc1.w};
    if (t < KCH) {   // single writer: plain stores
#pragma unroll
        for (int c = 0; c < 8; ++c) op[(size_t)c * HW_] = a[c];
    } else {
#pragma unroll
        for (int c = 0; c < 8; ++c) atomicAdd(op + (size_t)c * HW_, a[c]);
    }
}

extern "C" void kernel_launch(void* const* d_in, const int* in_sizes, int n_in,
                              void* d_out, int out_size)
{
    const float* flows  = (const float*)d_in[0];   // [2,24,2,64,64]
    const float* images = (const float*)d_in[1];   // [2,24,16,64,64]
    float*       out    = (float*)d_out;           // [2,24,16,64,64]

    // Zero only the atomically-accumulated region (t >= KCH).
    size_t skip = (size_t)KCH * C_ * HW_;
    for (int b = 0; b < B_; ++b) {
        float* p = out + (size_t)b * L_ * C_ * HW_;
        cudaMemsetAsync(p + skip, 0, ((size_t)L_ * C_ * HW_ - skip) * sizeof(float), 0);
    }

    prep_kernel<<<800, 256>>>(images, flows);      // transpose + cumsum, one launch

    dim3 grid(HW_ / 256, 60, B_ * 2);              // (16, 60, 4)
    gsp_kernel<<<grid, 256>>>(out);
}

// round 9
// speedup vs baseline: 1.1055x; 1.0052x over previous
#include <cuda_runtime.h>
#include <cuda_bf16.h>

#define B_  2
#define L_  24
#define C_  16
#define H_  64
#define W_  64
#define HW_ 4096
#define KCH 12

// Channel-grouped scratch: [B*L][4 groups][HW] float4 (4 channels per element).
__device__ float4 g_imgT[(size_t)B_ * L_ * 4 * HW_];
// Cumulative flow scratch: [B][L][HW] float2 (x,y per pixel).
__device__ float2 g_cum[(size_t)B_ * L_ * HW_];

// (t, k0) chunk table, chunks of <=KCH k's, sorted DESCENDING by length so the
// longest blocks get the lowest block ids (start in wave 1; drain tail short).
__constant__ short2 g_chunks[36] = {
    {11,0},{12,0},{13,0},{14,0},{15,0},{16,0},{17,0},{18,0},{19,0},{20,0},
    {21,0},{22,0},{23,0},{23,12},
    {10,0},{22,12},{9,0},{21,12},{8,0},{20,12},{7,0},{19,12},{6,0},{18,12},
    {5,0},{17,12},{4,0},{16,12},{3,0},{15,12},{2,0},{14,12},{1,0},{13,12},
    {0,0},{12,12}
};

// Merged prologue. Blocks [0, 768): NCHW -> group-of-4 transpose, 4 pixels
// per thread via a 4x4 register transpose (4x LDG.128 -> 4x STG.128).
// Blocks [768, 800): flow cumsum along L.
__global__ __launch_bounds__(256) void prep_kernel(
    const float* __restrict__ images,   // [B, L, C, H, W]
    const float* __restrict__ flows)    // [B, L, 2, H, W]
{
    const int bid = blockIdx.x;
    if (bid < 768) {
        const int id   = bid * 256 + threadIdx.x;
        const int pix4 = (id & 1023) * 4;         // 4-pixel base
        const int grp  = (id >> 10) & 3;
        const int bl   = id >> 12;                // 0..47
        const float4* src = (const float4*)(images + ((size_t)bl * C_ + grp * 4) * HW_ + pix4);
        float4 r0 = src[0];
        float4 r1 = src[HW_ / 4];
        float4 r2 = src[2 * (HW_ / 4)];
        float4 r3 = src[3 * (HW_ / 4)];
        float4* dst = g_imgT + ((size_t)bl * 4 + grp) * HW_ + pix4;
        dst[0] = make_float4(r0.x, r1.x, r2.x, r3.x);
        dst[1] = make_float4(r0.y, r1.y, r2.y, r3.y);
        dst[2] = make_float4(r0.z, r1.z, r2.z, r3.z);
        dst[3] = make_float4(r0.w, r1.w, r2.w, r3.w);
    } else {
        const int id  = (bid - 768) * 256 + threadIdx.x;   // 0..8191
        const int pix = id & (HW_ - 1);
        const int b   = id >> 12;
        const float* fp = flows + (size_t)b * L_ * 2 * HW_ + pix;
        float2* cp = g_cum + (size_t)b * L_ * HW_ + pix;
        float sx = 0.f, sy = 0.f;
#pragma unroll
        for (int k = 0; k < L_; ++k) {
            sx += fp[(size_t)k * 2 * HW_];
            sy += fp[(size_t)k * 2 * HW_ + HW_];
            cp[(size_t)k * HW_] = make_float2(sx, sy);
        }
    }
}

__device__ __forceinline__ void fma4(float4& a, float s, float4 v) {
    a.x += s * v.x; a.y += s * v.y; a.z += s * v.z; a.w += s * v.w;
}

// One bilinear-tap step for 8 channels (2 float4 groups).
__device__ __forceinline__ void gsp_step(
    int k, int w, int h, float2 cumt, const float2* __restrict__ cumb,
    const float4* __restrict__ g0base, float4& acc0, float4& acc1)
{
    const float2 ckf = cumb[(size_t)k * HW_];
    float relx = cumt.x - ckf.x;   // exactly 0 when k==t
    float rely = cumt.y - ckf.y;

    // align_corners=False: base grid == pixel centers
    float ix = (float)w + 32.f * relx;
    ix -= 64.f * floorf((ix + 0.5f) * 0.015625f);   // wrap x into [-0.5, 63.5)
    float iy = (float)h + 32.f * rely;

    float x0f = floorf(ix), y0f = floorf(iy);
    int   x0  = (int)x0f,   y0  = (int)y0f;
    float wx1 = ix - x0f,   wy1 = iy - y0f;
    float wx0 = 1.f - wx1,  wy0 = 1.f - wy1;

    // x0 in [-1, 63] by construction; x1 = x0+1 in [0, 64]
    bool vx0 = (x0 >= 0);
    bool vx1 = (x0 < W_ - 1);
    bool vy0 = (y0 >= 0) && (y0 <= H_ - 1);
    bool vy1 = (y0 >= -1) && (y0 < H_ - 1);

    float w00 = wx0 * wy0 * (float)(vx0 && vy0);
    float w01 = wx1 * wy0 * (float)(vx1 && vy0);
    float w10 = wx0 * wy1 * (float)(vx0 && vy1);
    float w11 = wx1 * wy1 * (float)(vx1 && vy1);

    int cx0 = max(x0, 0),              cx1 = min(x0 + 1, W_ - 1);
    int cy0 = min(max(y0, 0), H_ - 1), cy1 = min(max(y0 + 1, 0), H_ - 1);

    const int o00 = cy0 * W_ + cx0, o01 = cy0 * W_ + cx1;
    const int o10 = cy1 * W_ + cx0, o11 = cy1 * W_ + cx1;

    const float4* g0 = g0base + (size_t)k * 4 * HW_;   // group A plane for frame k
    const float4* g1 = g0 + HW_;                       // group B plane

    fma4(acc0, w00, g0[o00]); fma4(acc0, w01, g0[o01]);
    fma4(acc0, w10, g0[o10]); fma4(acc0, w11, g0[o11]);
    fma4(acc1, w00, g1[o00]); fma4(acc1, w01, g1[o01]);
    fma4(acc1, w10, g1[o10]); fma4(acc1, w11, g1[o11]);
}

// out[b,t,c,h,w] += sum_{k in chunk} bilinear taps (8 channels per thread).
// Grid = (pixtile, b*2+half, chunk-desc-sorted); <= KCH iterations per block.
__global__ __launch_bounds__(256, 6) void gsp_kernel(
    float* __restrict__ out)            // [B, L, C, H, W]
{
    const int b    = blockIdx.y >> 1;
    const int half = blockIdx.y & 1;          // 0 -> c0..7; 1 -> c8..15
    const short2 ck_ = g_chunks[blockIdx.z];
    const int t    = ck_.x;
    const int k0   = ck_.y;
    const int kend = min(k0 + KCH, t + 1);
    const int pix  = blockIdx.x * blockDim.x + threadIdx.x;
    const int h    = pix >> 6;
    const int w    = pix & 63;

    float4 acc0 = make_float4(0.f, 0.f, 0.f, 0.f);
    float4 acc1 = make_float4(0.f, 0.f, 0.f, 0.f);

    const float2* cumb = g_cum + (size_t)b * L_ * HW_ + pix;
    const float2 cumt = cumb[(size_t)t * HW_];
    const float4* g0base = g_imgT + ((size_t)b * L_ * 4 + half * 2) * HW_;

#pragma unroll 4
    for (int k = k0; k < kend; ++k)
        gsp_step(k, w, h, cumt, cumb, g0base, acc0, acc1);

    float* op = out + (((size_t)b * L_ + t) * C_ + half * 8) * HW_ + pix;
    float a[8] = {acc0.x, acc0.y, acc0.z, acc0.w, acc1.x, acc1.y, acc1.z, acc1.w};
    if (t < KCH) {   // single writer: plain stores
#pragma unroll
        for (int c = 0; c < 8; ++c) op[(size_t)c * HW_] = a[c];
    } else {
#pragma unroll
        for (int c = 0; c < 8; ++c) atomicAdd(op + (size_t)c * HW_, a[c]);
    }
}

extern "C" void kernel_launch(void* const* d_in, const int* in_sizes, int n_in,
                              void* d_out, int out_size)
{
    const float* flows  = (const float*)d_in[0];   // [2,24,2,64,64]
    const float* images = (const float*)d_in[1];   // [2,24,16,64,64]
    float*       out    = (float*)d_out;           // [2,24,16,64,64]

    // Zero only the atomically-accumulated region (t >= KCH).
    size_t skip = (size_t)KCH * C_ * HW_;
    for (int b = 0; b < B_; ++b) {
        float* p = out + (size_t)b * L_ * C_ * HW_;
        cudaMemsetAsync(p + skip, 0, ((size_t)L_ * C_ * HW_ - skip) * sizeof(float), 0);
    }

    prep_kernel<<<800, 256>>>(images, flows);      // transpose + cumsum, one launch

    dim3 grid(HW_ / 256, B_ * 2, 36);              // (16, 4, 36) — chunk outermost
    gsp_kernel<<<grid, 256>>>(out);
}

// round 11
// speedup vs baseline: 1.7572x; 1.5896x over previous
#include <cuda_runtime.h>
#include <cuda_fp16.h>

#define B_  2
#define L_  24
#define C_  16
#define H_  64
#define W_  64
#define HW_ 4096
#define KCH 12

// Packed-fp16 channel-grouped scratch: [B*L][2 halves][HW] x uint4
// (8 channels = 16 bytes per pixel per half).
__device__ uint4 g_imgH[(size_t)B_ * L_ * 2 * HW_];
// Cumulative flow scratch: [B][L][HW] float2 (x,y per pixel).
__device__ float2 g_cum[(size_t)B_ * L_ * HW_];

// (t, k0) chunk table, chunks of <=KCH k's, sorted DESCENDING by length so the
// longest blocks get the lowest block ids (start in wave 1; drain tail short).
__constant__ short2 g_chunks[36] = {
    {11,0},{12,0},{13,0},{14,0},{15,0},{16,0},{17,0},{18,0},{19,0},{20,0},
    {21,0},{22,0},{23,0},{23,12},
    {10,0},{22,12},{9,0},{21,12},{8,0},{20,12},{7,0},{19,12},{6,0},{18,12},
    {5,0},{17,12},{4,0},{16,12},{3,0},{15,12},{2,0},{14,12},{1,0},{13,12},
    {0,0},{12,12}
};

union U4H8 {
    uint4   u;
    __half2 h[4];
};

// Merged prologue. Blocks [0, 384): NCHW -> packed-fp16 8-channel transpose,
// 4 pixels per thread (8x LDG.128 -> register transpose -> 4x STG.128).
// Blocks [384, 416): flow cumsum along L.
__global__ __launch_bounds__(256) void prep_kernel(
    const float* __restrict__ images,   // [B, L, C, H, W]
    const float* __restrict__ flows)    // [B, L, 2, H, W]
{
    const int bid = blockIdx.x;
    if (bid < 384) {
        // linear id over (bl, half, pix4): 48 * 2 * 1024 = 98304 threads
        const int id   = bid * 256 + threadIdx.x;
        const int pix4 = (id & 1023) * 4;         // 4-pixel base
        const int half = (id >> 10) & 1;
        const int bl   = id >> 11;                // 0..47
        const float4* src = (const float4*)(images + ((size_t)bl * C_ + half * 8) * HW_ + pix4);
        float4 r[8];
#pragma unroll
        for (int c = 0; c < 8; ++c) r[c] = src[(size_t)c * (HW_ / 4)];

        uint4* dst = g_imgH + ((size_t)bl * 2 + half) * HW_ + pix4;
#pragma unroll
        for (int j = 0; j < 4; ++j) {
            const float* f = (const float*)r;     // r[c] component j = f[c*4 + j]
            U4H8 o;
            o.h[0] = __floats2half2_rn(f[0*4 + j], f[1*4 + j]);
            o.h[1] = __floats2half2_rn(f[2*4 + j], f[3*4 + j]);
            o.h[2] = __floats2half2_rn(f[4*4 + j], f[5*4 + j]);
            o.h[3] = __floats2half2_rn(f[6*4 + j], f[7*4 + j]);
            dst[j] = o.u;
        }
    } else {
        const int id  = (bid - 384) * 256 + threadIdx.x;   // 0..8191
        const int pix = id & (HW_ - 1);
        const int b   = id >> 12;
        const float* fp = flows + (size_t)b * L_ * 2 * HW_ + pix;
        float2* cp = g_cum + (size_t)b * L_ * HW_ + pix;
        float sx = 0.f, sy = 0.f;
#pragma unroll
        for (int k = 0; k < L_; ++k) {
            sx += fp[(size_t)k * 2 * HW_];
            sy += fp[(size_t)k * 2 * HW_ + HW_];
            cp[(size_t)k * HW_] = make_float2(sx, sy);
        }
    }
}

// acc[0..7] += s * unpack_fp16x8(v)
__device__ __forceinline__ void fmah8(float acc[8], float s, uint4 v) {
    const __half2* hp = reinterpret_cast<const __half2*>(&v);
    float2 f0 = __half22float2(hp[0]);
    float2 f1 = __half22float2(hp[1]);
    float2 f2 = __half22float2(hp[2]);
    float2 f3 = __half22float2(hp[3]);
    acc[0] += s * f0.x; acc[1] += s * f0.y;
    acc[2] += s * f1.x; acc[3] += s * f1.y;
    acc[4] += s * f2.x; acc[5] += s * f2.y;
    acc[6] += s * f3.x; acc[7] += s * f3.y;
}

// One bilinear-tap step for 8 channels (one uint4 per corner).
__device__ __forceinline__ void gsp_step(
    int k, int w, int h, float2 cumt, const float2* __restrict__ cumb,
    const uint4* __restrict__ gbase, float acc[8])
{
    const float2 ckf = cumb[(size_t)k * HW_];
    float relx = cumt.x - ckf.x;   // exactly 0 when k==t
    float rely = cumt.y - ckf.y;

    // align_corners=False: base grid == pixel centers
    float ix = (float)w + 32.f * relx;
    ix -= 64.f * floorf((ix + 0.5f) * 0.015625f);   // wrap x into [-0.5, 63.5)
    float iy = (float)h + 32.f * rely;

    float x0f = floorf(ix), y0f = floorf(iy);
    int   x0  = (int)x0f,   y0  = (int)y0f;
    float wx1 = ix - x0f,   wy1 = iy - y0f;
    float wx0 = 1.f - wx1,  wy0 = 1.f - wy1;

    // x0 in [-1, 63] by construction; x1 = x0+1 in [0, 64]
    bool vx0 = (x0 >= 0);
    bool vx1 = (x0 < W_ - 1);
    bool vy0 = (y0 >= 0) && (y0 <= H_ - 1);
    bool vy1 = (y0 >= -1) && (y0 < H_ - 1);

    float w00 = wx0 * wy0 * (float)(vx0 && vy0);
    float w01 = wx1 * wy0 * (float)(vx1 && vy0);
    float w10 = wx0 * wy1 * (float)(vx0 && vy1);
    float w11 = wx1 * wy1 * (float)(vx1 && vy1);

    int cx0 = max(x0, 0),              cx1 = min(x0 + 1, W_ - 1);
    int cy0 = min(max(y0, 0), H_ - 1), cy1 = min(max(y0 + 1, 0), H_ - 1);

    const uint4* gk = gbase + (size_t)k * 2 * HW_;
    uint4 v00 = gk[cy0 * W_ + cx0];
    uint4 v01 = gk[cy0 * W_ + cx1];
    uint4 v10 = gk[cy1 * W_ + cx0];
    uint4 v11 = gk[cy1 * W_ + cx1];

    fmah8(acc, w00, v00);
    fmah8(acc, w01, v01);
    fmah8(acc, w10, v10);
    fmah8(acc, w11, v11);
}

// out[b,t,c,h,w] += sum_{k in chunk} bilinear taps (8 channels per thread).
// Grid = (pixtile, b*2+half, chunk-desc-sorted); <= KCH iterations per block.
__global__ __launch_bounds__(256, 6) void gsp_kernel(
    float* __restrict__ out)            // [B, L, C, H, W]
{
    const int b    = blockIdx.y >> 1;
    const int half = blockIdx.y & 1;          // 0 -> c0..7; 1 -> c8..15
    const short2 ck_ = g_chunks[blockIdx.z];
    const int t    = ck_.x;
    const int k0   = ck_.y;
    const int kend = min(k0 + KCH, t + 1);
    const int pix  = blockIdx.x * blockDim.x + threadIdx.x;
    const int h    = pix >> 6;
    const int w    = pix & 63;

    float acc[8];
#pragma unroll
    for (int c = 0; c < 8; ++c) acc[c] = 0.f;

    const float2* cumb = g_cum + (size_t)b * L_ * HW_ + pix;
    const float2 cumt = cumb[(size_t)t * HW_];
    const uint4* gbase = g_imgH + ((size_t)b * L_ * 2 + half) * HW_;

#pragma unroll 4
    for (int k = k0; k < kend; ++k)
        gsp_step(k, w, h, cumt, cumb, gbase, acc);

    float* op = out + (((size_t)b * L_ + t) * C_ + half * 8) * HW_ + pix;
    if (t < KCH) {   // single writer: plain stores
#pragma unroll
        for (int c = 0; c < 8; ++c) op[(size_t)c * HW_] = acc[c];
    } else {
#pragma unroll
        for (int c = 0; c < 8; ++c) atomicAdd(op + (size_t)c * HW_, acc[c]);
    }
}

extern "C" void kernel_launch(void* const* d_in, const int* in_sizes, int n_in,
                              void* d_out, int out_size)
{
    const float* flows  = (const float*)d_in[0];   // [2,24,2,64,64]
    const float* images = (const float*)d_in[1];   // [2,24,16,64,64]
    float*       out    = (float*)d_out;           // [2,24,16,64,64]

    // Zero only the atomically-accumulated region (t >= KCH).
    size_t skip = (size_t)KCH * C_ * HW_;
    for (int b = 0; b < B_; ++b) {
        float* p = out + (size_t)b * L_ * C_ * HW_;
        cudaMemsetAsync(p + skip, 0, ((size_t)L_ * C_ * HW_ - skip) * sizeof(float), 0);
    }

    prep_kernel<<<416, 256>>>(images, flows);      // fp16 transpose + cumsum

    dim3 grid(HW_ / 256, B_ * 2, 36);              // (16, 4, 36) — chunk outermost
    gsp_kernel<<<grid, 256>>>(out);
}